// round 1
// baseline (speedup 1.0000x reference)
#include <cuda_runtime.h>
#include <cstdint>

#define N_NODES 8192
#define IN_DIM  64
#define MLP_HID 128
#define EMB     512
#define HID     1024
#define G3      (3*HID)
#define N_TYPES 16

// ---------------- scratch (device globals; no allocation allowed) ----------
__device__ float g_emb [N_NODES*EMB];          // 16 MB
__device__ float g_gi0 [(size_t)N_NODES*G3];   // 100 MB
__device__ float g_out0[(size_t)N_NODES*HID];  // 32 MB
__device__ float g_gi1 [(size_t)N_NODES*G3];   // 100 MB
__device__ float g_out1[(size_t)N_NODES*HID];  // 32 MB
__device__ unsigned g_ctr0;
__device__ unsigned g_ctr1;

__global__ void reset_counters()
{
    g_ctr0 = 0u;
    g_ctr1 = 0u;
}

// ---------------- expert MLP: emb = relu(x@W1[t]+b1[t]) @ W2[t] + b2[t] ----
__global__ void mlp_kernel(const float* __restrict__ feats,
                           const int*   __restrict__ types,
                           const float* __restrict__ W1,
                           const float* __restrict__ b1,
                           const float* __restrict__ W2,
                           const float* __restrict__ b2)
{
    __shared__ float xs[IN_DIM];
    __shared__ float h1[MLP_HID];
    const int n   = blockIdx.x;
    const int tid = threadIdx.x;           // 128 threads
    const int ty  = types[n];

    if (tid < IN_DIM) xs[tid] = feats[(size_t)n*IN_DIM + tid];
    __syncthreads();

    // hidden: 128 outputs, one per thread
    {
        const float* w = W1 + (size_t)ty*IN_DIM*MLP_HID;
        float acc = b1[ty*MLP_HID + tid];
        #pragma unroll 8
        for (int i = 0; i < IN_DIM; i++)
            acc += xs[i] * w[i*MLP_HID + tid];
        h1[tid] = fmaxf(acc, 0.0f);
    }
    __syncthreads();

    // emb: 512 outputs, 4 per thread (coalesced across tid)
    {
        const float* w = W2 + (size_t)ty*MLP_HID*EMB;
        #pragma unroll
        for (int e0 = 0; e0 < 4; e0++) {
            const int e = e0*MLP_HID + tid;
            float acc = b2[ty*EMB + e];
            #pragma unroll 8
            for (int i = 0; i < MLP_HID; i++)
                acc += h1[i] * w[i*EMB + e];
            g_emb[(size_t)n*EMB + e] = acc;
        }
    }
}

// ---------------- generic Out[N,3H] = X[N,K] @ W[3H,K]^T + b --------------
#define BM 64
#define BN 64
#define BK 16
__global__ void gemm_xwT(int whichX,               // 0: g_emb (K=512), 1: g_out0 (K=1024)
                         const float* __restrict__ W,
                         const float* __restrict__ bias,
                         int K)
{
    const float* X   = whichX ? g_out0 : g_emb;
    float*       Out = whichX ? g_gi1  : g_gi0;
    const int M = G3;

    __shared__ float Xs[BK][BM + 4];
    __shared__ float Ws[BK][BN + 4];

    const int bn0 = blockIdx.y * BM;     // rows of X (n)
    const int bm0 = blockIdx.x * BN;     // rows of W (m)
    const int tid = threadIdx.x;         // 256
    const int tx  = tid & 15;
    const int ty  = tid >> 4;

    const int lr = tid >> 2;             // 0..63
    const int lc = (tid & 3) * 4;        // 0,4,8,12

    float acc[4][4] = {};

    for (int k0 = 0; k0 < K; k0 += BK) {
        float4 xv = *(const float4*)(X + (size_t)(bn0 + lr)*K + k0 + lc);
        float4 wv = *(const float4*)(W + (size_t)(bm0 + lr)*K + k0 + lc);
        Xs[lc+0][lr] = xv.x; Xs[lc+1][lr] = xv.y; Xs[lc+2][lr] = xv.z; Xs[lc+3][lr] = xv.w;
        Ws[lc+0][lr] = wv.x; Ws[lc+1][lr] = wv.y; Ws[lc+2][lr] = wv.z; Ws[lc+3][lr] = wv.w;
        __syncthreads();
        #pragma unroll
        for (int kk = 0; kk < BK; kk++) {
            float a[4], b[4];
            #pragma unroll
            for (int i = 0; i < 4; i++) a[i] = Xs[kk][ty*4 + i];
            #pragma unroll
            for (int i = 0; i < 4; i++) b[i] = Ws[kk][tx*4 + i];
            #pragma unroll
            for (int i = 0; i < 4; i++)
                #pragma unroll
                for (int j = 0; j < 4; j++)
                    acc[i][j] += a[i] * b[j];
        }
        __syncthreads();
    }
    #pragma unroll
    for (int i = 0; i < 4; i++) {
        const size_t row = (size_t)(bn0 + ty*4 + i) * M;
        #pragma unroll
        for (int j = 0; j < 4; j++) {
            const int m = bm0 + tx*4 + j;
            Out[row + m] = acc[i][j] + bias[m];
        }
    }
}

// ---------------- recurrent scan (persistent, grid-wide barrier) -----------
// grid = 128 CTAs x 256 threads; warp w of CTA b owns hidden unit j = b*8+w.
// Whh rows (r,z,n) for unit j are held in registers (96 floats / lane).
#define SCAN_CTAS 128

__global__ void __launch_bounds__(256) scan_kernel(int which,                // 0: layer0, 1: layer1
                                                   const float* __restrict__ Whh,
                                                   const float* __restrict__ bhh,
                                                   const float* __restrict__ h0)
{
    const float* gi  = which ? g_gi1  : g_gi0;
    float*       out = which ? g_out1 : g_out0;
    unsigned*    ctr = which ? &g_ctr1 : &g_ctr0;

    __shared__ float hsh[HID];
    const int tid  = threadIdx.x;
    const int warp = tid >> 5;
    const int lane = tid & 31;
    const int j    = blockIdx.x * 8 + warp;      // 0..1023

    // load the 3 weight rows for unit j into registers
    float wr[32], wz[32], wn[32];
    {
        const float4* R = (const float4*)(Whh + (size_t) j         * HID);
        const float4* Z = (const float4*)(Whh + (size_t)(j +   HID) * HID);
        const float4* Nw= (const float4*)(Whh + (size_t)(j + 2*HID) * HID);
        #pragma unroll
        for (int u = 0; u < 8; u++) {
            float4 a = R [u*32 + lane]; wr[u*4+0]=a.x; wr[u*4+1]=a.y; wr[u*4+2]=a.z; wr[u*4+3]=a.w;
            float4 b = Z [u*32 + lane]; wz[u*4+0]=b.x; wz[u*4+1]=b.y; wz[u*4+2]=b.z; wz[u*4+3]=b.w;
            float4 c = Nw[u*32 + lane]; wn[u*4+0]=c.x; wn[u*4+1]=c.y; wn[u*4+2]=c.z; wn[u*4+3]=c.w;
        }
    }
    const float br  = bhh[j];
    const float bz  = bhh[j + HID];
    const float bnn = bhh[j + 2*HID];
    const unsigned G = gridDim.x;

    for (int t = 0; t < N_NODES; t++) {
        // stage h_{t-1} into shared (bypass L1: rows written by other SMs)
        {
            const float4* hp = (t == 0) ? (const float4*)h0
                                        : (const float4*)(out + (size_t)(t-1)*HID);
            float4 v = __ldcg(hp + tid);
            ((float4*)hsh)[tid] = v;
        }
        __syncthreads();

        float ar = 0.f, az = 0.f, an = 0.f;
        #pragma unroll
        for (int u = 0; u < 8; u++) {
            float4 h4 = ((const float4*)hsh)[u*32 + lane];
            ar += wr[u*4+0]*h4.x + wr[u*4+1]*h4.y + wr[u*4+2]*h4.z + wr[u*4+3]*h4.w;
            az += wz[u*4+0]*h4.x + wz[u*4+1]*h4.y + wz[u*4+2]*h4.z + wz[u*4+3]*h4.w;
            an += wn[u*4+0]*h4.x + wn[u*4+1]*h4.y + wn[u*4+2]*h4.z + wn[u*4+3]*h4.w;
        }
        #pragma unroll
        for (int o = 16; o; o >>= 1) {
            ar += __shfl_xor_sync(0xffffffffu, ar, o);
            az += __shfl_xor_sync(0xffffffffu, az, o);
            an += __shfl_xor_sync(0xffffffffu, an, o);
        }
        if (lane == 0) {
            const float* g = gi + (size_t)t * G3;
            const float r = 1.0f / (1.0f + __expf(-(g[j]         + ar + br )));
            const float z = 1.0f / (1.0f + __expf(-(g[j +   HID] + az + bz )));
            const float n = tanhf(          g[j + 2*HID] + r * (an + bnn));
            out[(size_t)t*HID + j] = (1.0f - z) * n + z * hsh[j];
        }

        // grid-wide step barrier
        __threadfence();
        __syncthreads();
        if (tid == 0) {
            atomicAdd(ctr, 1u);
            const unsigned target = G * (unsigned)(t + 1);
            unsigned v;
            do {
                asm volatile("ld.global.acquire.gpu.u32 %0, [%1];"
                             : "=r"(v) : "l"(ctr) : "memory");
            } while (v < target);
        }
        __syncthreads();
    }
}

// ---------------- final FC: out = fc_W @ last + fc_b -----------------------
__global__ void fc_kernel(const float* __restrict__ fcW,
                          const float* __restrict__ fcb,
                          float* __restrict__ outv)
{
    const int tid  = threadIdx.x;
    const int warp = tid >> 5;
    const int lane = tid & 31;
    const int j    = blockIdx.x * 8 + warp;     // 0..1023
    const float* last = g_out1 + (size_t)(N_NODES - 1) * HID;
    const float* w    = fcW + (size_t)j * HID;
    float a = 0.f;
    #pragma unroll 8
    for (int k = lane; k < HID; k += 32) a += w[k] * last[k];
    #pragma unroll
    for (int o = 16; o; o >>= 1) a += __shfl_xor_sync(0xffffffffu, a, o);
    if (lane == 0) outv[j] = a + fcb[j];
}

// ---------------- launch ---------------------------------------------------
extern "C" void kernel_launch(void* const* d_in, const int* in_sizes, int n_in,
                              void* d_out, int out_size)
{
    const float* node_feats = (const float*)d_in[0];
    const int*   node_types = (const int*)  d_in[1];
    const float* W1   = (const float*)d_in[2];
    const float* b1   = (const float*)d_in[3];
    const float* W2   = (const float*)d_in[4];
    const float* b2   = (const float*)d_in[5];
    const float* Wih0 = (const float*)d_in[6];
    const float* Whh0 = (const float*)d_in[7];
    const float* bih0 = (const float*)d_in[8];
    const float* bhh0 = (const float*)d_in[9];
    const float* Wih1 = (const float*)d_in[10];
    const float* Whh1 = (const float*)d_in[11];
    const float* bih1 = (const float*)d_in[12];
    const float* bhh1 = (const float*)d_in[13];
    const float* h_init = (const float*)d_in[14];
    const float* fc_W = (const float*)d_in[15];
    const float* fc_b = (const float*)d_in[16];
    float* outv = (float*)d_out;

    reset_counters<<<1, 1>>>();

    // expert MLP -> g_emb
    mlp_kernel<<<N_NODES, 128>>>(node_feats, node_types, W1, b1, W2, b2);

    // gi0 = emb @ Wih0^T + bih0   (K = EMB = 512)
    {
        dim3 grid(G3 / BN, N_NODES / BM);
        gemm_xwT<<<grid, 256>>>(0, Wih0, bih0, EMB);
    }

    // layer-0 scan -> g_out0
    scan_kernel<<<SCAN_CTAS, 256>>>(0, Whh0, bhh0, h_init);

    // gi1 = out0 @ Wih1^T + bih1  (K = HID = 1024)
    {
        dim3 grid(G3 / BN, N_NODES / BM);
        gemm_xwT<<<grid, 256>>>(1, Wih1, bih1, HID);
    }

    // layer-1 scan -> g_out1
    scan_kernel<<<SCAN_CTAS, 256>>>(1, Whh1, bhh1, h_init + HID);

    // final FC on the last timestep
    fc_kernel<<<HID / 8, 256>>>(fc_W, fc_b, outv);
}

// round 3
// speedup vs baseline: 1.3395x; 1.3395x over previous
#include <cuda_runtime.h>
#include <cstdint>

#define N_NODES 8192
#define IN_DIM  64
#define MLP_HID 128
#define EMB     512
#define HID     1024
#define G3      (3*HID)
#define N_TYPES 16

// ---------------- scratch (device globals; no allocation allowed) ----------
__device__ float g_emb [(size_t)N_NODES*EMB];    // 16 MB
__device__ float g_gi0 [(size_t)N_NODES*G3];     // 100 MB
__device__ float g_gi1 [(size_t)N_NODES*G3];     // 100 MB
__device__ float g_out0[(size_t)N_NODES*HID];    // 32 MB (plain, for gi1 GEMM)
__device__ unsigned long long g_h0t[(size_t)N_NODES*HID];  // 64 MB {tag32|val32}
__device__ unsigned long long g_h1t[(size_t)N_NODES*HID];  // 64 MB {tag32|val32}

// ---------------- clear tag buffers (must run before scans) ----------------
__global__ void clear_tags()
{
    const size_t n = (size_t)N_NODES * HID;
    const size_t stride = (size_t)gridDim.x * blockDim.x;
    for (size_t i = (size_t)blockIdx.x * blockDim.x + threadIdx.x; i < n; i += stride) {
        g_h0t[i] = 0ull;
        g_h1t[i] = 0ull;
    }
}

// ---------------- expert MLP: emb = relu(x@W1[t]+b1[t]) @ W2[t] + b2[t] ----
__global__ void mlp_kernel(const float* __restrict__ feats,
                           const int*   __restrict__ types,
                           const float* __restrict__ W1,
                           const float* __restrict__ b1,
                           const float* __restrict__ W2,
                           const float* __restrict__ b2)
{
    __shared__ float xs[IN_DIM];
    __shared__ float h1[MLP_HID];
    const int n   = blockIdx.x;
    const int tid = threadIdx.x;           // 128 threads
    const int ty  = types[n];

    if (tid < IN_DIM) xs[tid] = feats[(size_t)n*IN_DIM + tid];
    __syncthreads();

    {
        const float* w = W1 + (size_t)ty*IN_DIM*MLP_HID;
        float acc = b1[ty*MLP_HID + tid];
        #pragma unroll 8
        for (int i = 0; i < IN_DIM; i++)
            acc += xs[i] * w[i*MLP_HID + tid];
        h1[tid] = fmaxf(acc, 0.0f);
    }
    __syncthreads();

    {
        const float* w = W2 + (size_t)ty*MLP_HID*EMB;
        #pragma unroll
        for (int e0 = 0; e0 < 4; e0++) {
            const int e = e0*MLP_HID + tid;
            float acc = b2[ty*EMB + e];
            #pragma unroll 8
            for (int i = 0; i < MLP_HID; i++)
                acc += h1[i] * w[i*EMB + e];
            g_emb[(size_t)n*EMB + e] = acc;
        }
    }
}

// -------- GEMM: Out[8192,3072] = X[8192,K] @ W[3072,K]^T + bias ------------
// 128x128 tile, BK=8, 256 threads, 8x8 microtile, double-buffered smem.
#define GBM 128
#define GBN 128
#define GBK 8

__global__ void __launch_bounds__(256) gemm_kernel(const float* __restrict__ X,
                                                   const float* __restrict__ W,
                                                   const float* __restrict__ bias,
                                                   float* __restrict__ Out,
                                                   int K)
{
    __shared__ float As[2][GBK][GBM];
    __shared__ float Bs[2][GBK][GBN];

    const int tid  = threadIdx.x;        // 256
    const int tx   = tid & 15;
    const int ty   = tid >> 4;
    const int row0 = blockIdx.y * GBM;   // X rows
    const int col0 = blockIdx.x * GBN;   // W rows (output cols)
    const int lr   = tid >> 1;           // 0..127
    const int lc   = (tid & 1) * 4;      // 0 or 4

    const float* Xp = X + (size_t)(row0 + lr) * K + lc;
    const float* Wp = W + (size_t)(col0 + lr) * K + lc;

    float4 xa = *(const float4*)Xp;
    float4 wa = *(const float4*)Wp;
    As[0][lc+0][lr]=xa.x; As[0][lc+1][lr]=xa.y; As[0][lc+2][lr]=xa.z; As[0][lc+3][lr]=xa.w;
    Bs[0][lc+0][lr]=wa.x; Bs[0][lc+1][lr]=wa.y; Bs[0][lc+2][lr]=wa.z; Bs[0][lc+3][lr]=wa.w;
    __syncthreads();

    float acc[8][8] = {};
    const int nk = K / GBK;
    int cur = 0;

    for (int kt = 0; kt < nk; kt++) {
        if (kt + 1 < nk) {
            xa = *(const float4*)(Xp + (size_t)(kt+1)*GBK);
            wa = *(const float4*)(Wp + (size_t)(kt+1)*GBK);
        }
        #pragma unroll
        for (int kk = 0; kk < GBK; kk++) {
            float a[8], b[8];
            *(float4*)(a  ) = *(const float4*)&As[cur][kk][ty*8    ];
            *(float4*)(a+4) = *(const float4*)&As[cur][kk][ty*8 + 4];
            *(float4*)(b  ) = *(const float4*)&Bs[cur][kk][tx*8    ];
            *(float4*)(b+4) = *(const float4*)&Bs[cur][kk][tx*8 + 4];
            #pragma unroll
            for (int i = 0; i < 8; i++)
                #pragma unroll
                for (int j = 0; j < 8; j++)
                    acc[i][j] += a[i] * b[j];
        }
        if (kt + 1 < nk) {
            const int nxt = cur ^ 1;
            As[nxt][lc+0][lr]=xa.x; As[nxt][lc+1][lr]=xa.y; As[nxt][lc+2][lr]=xa.z; As[nxt][lc+3][lr]=xa.w;
            Bs[nxt][lc+0][lr]=wa.x; Bs[nxt][lc+1][lr]=wa.y; Bs[nxt][lc+2][lr]=wa.z; Bs[nxt][lc+3][lr]=wa.w;
            __syncthreads();
            cur = nxt;
        }
    }

    float bj[8];
    #pragma unroll
    for (int j = 0; j < 8; j++) bj[j] = bias[col0 + tx*8 + j];

    #pragma unroll
    for (int i = 0; i < 8; i++) {
        float* o = Out + (size_t)(row0 + ty*8 + i) * G3 + col0 + tx*8;
        float4 v0 = make_float4(acc[i][0]+bj[0], acc[i][1]+bj[1], acc[i][2]+bj[2], acc[i][3]+bj[3]);
        float4 v1 = make_float4(acc[i][4]+bj[4], acc[i][5]+bj[5], acc[i][6]+bj[6], acc[i][7]+bj[7]);
        *(float4*)(o    ) = v0;
        *(float4*)(o + 4) = v1;
    }
}

// ---------------- recurrent scan: single-b64 tagged data-flow sync ---------
// 128 CTAs x 256 thr; warp w of CTA b owns unit j = b*8+w; Whh rows in regs.
// h[t][j] published as one relaxed.gpu b64 {tag=t+1 | fp32 value}: strong
// scoped 8B accesses are single-copy atomic -> tag and value can never tear.
#define SCAN_CTAS 128

__global__ void __launch_bounds__(256, 1) scan_kernel(const float* __restrict__ gi,
                                                      const float* __restrict__ Whh,
                                                      const float* __restrict__ bhh,
                                                      const float* __restrict__ h0,
                                                      unsigned long long* __restrict__ htag,
                                                      float* __restrict__ hplain)
{
    __shared__ float hsh[HID];
    const int tid  = threadIdx.x;
    const int warp = tid >> 5;
    const int lane = tid & 31;
    const int j    = blockIdx.x * 8 + warp;      // 0..1023

    // load the 3 weight rows for unit j into registers (96 floats / lane)
    float wr[32], wz[32], wn[32];
    {
        const float4* R  = (const float4*)(Whh + (size_t) j          * HID);
        const float4* Z  = (const float4*)(Whh + (size_t)(j +   HID) * HID);
        const float4* Nw = (const float4*)(Whh + (size_t)(j + 2*HID) * HID);
        #pragma unroll
        for (int u = 0; u < 8; u++) {
            float4 a = R [u*32 + lane]; wr[u*4+0]=a.x; wr[u*4+1]=a.y; wr[u*4+2]=a.z; wr[u*4+3]=a.w;
            float4 b = Z [u*32 + lane]; wz[u*4+0]=b.x; wz[u*4+1]=b.y; wz[u*4+2]=b.z; wz[u*4+3]=b.w;
            float4 c = Nw[u*32 + lane]; wn[u*4+0]=c.x; wn[u*4+1]=c.y; wn[u*4+2]=c.z; wn[u*4+3]=c.w;
        }
    }
    const float br  = bhh[j];
    const float bz  = bhh[j + HID];
    const float bnn = bhh[j + 2*HID];

    for (int t = 0; t < N_NODES; t++) {
        // gate-input loads issue early (independent of h polling)
        float gr = 0.f, gz = 0.f, gn = 0.f;
        if (lane == 0) {
            const float* g = gi + (size_t)t * G3;
            gr = __ldg(g + j);
            gz = __ldg(g + j + HID);
            gn = __ldg(g + j + 2*HID);
        }

        // stage h_{t-1} into shared
        if (t == 0) {
            ((float4*)hsh)[tid] = ((const float4*)h0)[tid];
        } else {
            const unsigned long long* src = htag + (size_t)(t-1) * HID + 4*tid;
            const unsigned want = (unsigned)t;     // tag stored at step t-1 is (t-1)+1 = t
            unsigned long long w0, w1, w2, w3;
            do {
                asm volatile("ld.global.relaxed.gpu.b64 %0, [%1];"
                             : "=l"(w0) : "l"(src + 0) : "memory");
                asm volatile("ld.global.relaxed.gpu.b64 %0, [%1];"
                             : "=l"(w1) : "l"(src + 1) : "memory");
                asm volatile("ld.global.relaxed.gpu.b64 %0, [%1];"
                             : "=l"(w2) : "l"(src + 2) : "memory");
                asm volatile("ld.global.relaxed.gpu.b64 %0, [%1];"
                             : "=l"(w3) : "l"(src + 3) : "memory");
            } while ((unsigned)(w0 >> 32) != want || (unsigned)(w1 >> 32) != want ||
                     (unsigned)(w2 >> 32) != want || (unsigned)(w3 >> 32) != want);
            const int e0 = 4*tid;
            hsh[e0+0] = __uint_as_float((unsigned)w0);
            hsh[e0+1] = __uint_as_float((unsigned)w1);
            hsh[e0+2] = __uint_as_float((unsigned)w2);
            hsh[e0+3] = __uint_as_float((unsigned)w3);
        }
        __syncthreads();

        float ar = 0.f, az = 0.f, an = 0.f;
        #pragma unroll
        for (int u = 0; u < 8; u++) {
            float4 h4 = ((const float4*)hsh)[u*32 + lane];
            ar += wr[u*4+0]*h4.x + wr[u*4+1]*h4.y + wr[u*4+2]*h4.z + wr[u*4+3]*h4.w;
            az += wz[u*4+0]*h4.x + wz[u*4+1]*h4.y + wz[u*4+2]*h4.z + wz[u*4+3]*h4.w;
            an += wn[u*4+0]*h4.x + wn[u*4+1]*h4.y + wn[u*4+2]*h4.z + wn[u*4+3]*h4.w;
        }
        #pragma unroll
        for (int o = 16; o; o >>= 1) {
            ar += __shfl_xor_sync(0xffffffffu, ar, o);
            az += __shfl_xor_sync(0xffffffffu, az, o);
            an += __shfl_xor_sync(0xffffffffu, an, o);
        }
        if (lane == 0) {
            const float r = 1.0f / (1.0f + __expf(-(gr + ar + br )));
            const float z = 1.0f / (1.0f + __expf(-(gz + az + bz )));
            const float n = tanhf(gn + r * (an + bnn));
            const float hnew = (1.0f - z) * n + z * hsh[j];
            const unsigned long long w =
                (unsigned long long)__float_as_uint(hnew) |
                ((unsigned long long)(unsigned)(t + 1) << 32);
            asm volatile("st.global.relaxed.gpu.b64 [%0], %1;"
                         :: "l"(htag + (size_t)t*HID + j), "l"(w) : "memory");
            if (hplain) hplain[(size_t)t*HID + j] = hnew;
        }
        __syncthreads();   // protect hsh before next staging
    }
}

// ---------------- final FC: out = fc_W @ last + fc_b -----------------------
__global__ void fc_kernel(const float* __restrict__ fcW,
                          const float* __restrict__ fcb,
                          float* __restrict__ outv)
{
    const int tid  = threadIdx.x;
    const int warp = tid >> 5;
    const int lane = tid & 31;
    const int j    = blockIdx.x * 8 + warp;     // 0..1023
    const unsigned long long* last = g_h1t + (size_t)(N_NODES - 1) * HID;
    const float* w = fcW + (size_t)j * HID;
    float a = 0.f;
    #pragma unroll 8
    for (int k = lane; k < HID; k += 32)
        a += w[k] * __uint_as_float((unsigned)last[k]);
    #pragma unroll
    for (int o = 16; o; o >>= 1) a += __shfl_xor_sync(0xffffffffu, a, o);
    if (lane == 0) outv[j] = a + fcb[j];
}

// ---------------- launch ---------------------------------------------------
extern "C" void kernel_launch(void* const* d_in, const int* in_sizes, int n_in,
                              void* d_out, int out_size)
{
    const float* node_feats = (const float*)d_in[0];
    const int*   node_types = (const int*)  d_in[1];
    const float* W1   = (const float*)d_in[2];
    const float* b1   = (const float*)d_in[3];
    const float* W2   = (const float*)d_in[4];
    const float* b2   = (const float*)d_in[5];
    const float* Wih0 = (const float*)d_in[6];
    const float* Whh0 = (const float*)d_in[7];
    const float* bih0 = (const float*)d_in[8];
    const float* bhh0 = (const float*)d_in[9];
    const float* Wih1 = (const float*)d_in[10];
    const float* Whh1 = (const float*)d_in[11];
    const float* bih1 = (const float*)d_in[12];
    const float* bhh1 = (const float*)d_in[13];
    const float* h_init = (const float*)d_in[14];
    const float* fc_W = (const float*)d_in[15];
    const float* fc_b = (const float*)d_in[16];
    float* outv = (float*)d_out;

    float* p_emb;  cudaGetSymbolAddress((void**)&p_emb,  g_emb);
    float* p_gi0;  cudaGetSymbolAddress((void**)&p_gi0,  g_gi0);
    float* p_gi1;  cudaGetSymbolAddress((void**)&p_gi1,  g_gi1);
    float* p_out0; cudaGetSymbolAddress((void**)&p_out0, g_out0);
    unsigned long long* p_h0t; cudaGetSymbolAddress((void**)&p_h0t, g_h0t);
    unsigned long long* p_h1t; cudaGetSymbolAddress((void**)&p_h1t, g_h1t);

    // clear tag buffers (stream-ordered before scans; required every replay)
    clear_tags<<<2048, 256>>>();

    // expert MLP -> g_emb
    mlp_kernel<<<N_NODES, 128>>>(node_feats, node_types, W1, b1, W2, b2);

    // gi0 = emb @ Wih0^T + bih0   (K = EMB = 512)
    {
        dim3 grid(G3 / GBN, N_NODES / GBM);
        gemm_kernel<<<grid, 256>>>(p_emb, Wih0, bih0, p_gi0, EMB);
    }

    // layer-0 scan -> g_h0t (tagged) + g_out0 (plain)
    scan_kernel<<<SCAN_CTAS, 256>>>(p_gi0, Whh0, bhh0, h_init, p_h0t, p_out0);

    // gi1 = out0 @ Wih1^T + bih1  (K = HID = 1024)
    {
        dim3 grid(G3 / GBN, N_NODES / GBM);
        gemm_kernel<<<grid, 256>>>(p_out0, Wih1, bih1, p_gi1, HID);
    }

    // layer-1 scan -> g_h1t (tagged)
    scan_kernel<<<SCAN_CTAS, 256>>>(p_gi1, Whh1, bhh1, h_init + HID, p_h1t, (float*)0);

    // final FC on the last timestep
    fc_kernel<<<HID / 8, 256>>>(fc_W, fc_b, outv);
}